// round 16
// baseline (speedup 1.0000x reference)
#include <cuda_runtime.h>
#include <cstdint>

// Problem constants (fixed by the dataset)
#define N_NODES 50000
#define N_EDGES 800000
#define IN_C    512
#define HID_C   512
#define OUT_C   256

#define SCAN_BLK 512
#define NB_SCAN  ((N_NODES + SCAN_BLK - 1) / SCAN_BLK)   // 98

// ---------------------------------------------------------------------------
// Scratch: __device__ globals, referenced directly inside kernels.
// (No tensor-core instructions anywhere: modules containing ldmatrix/mma.sync
// trigger a fixed 128MiB driver allocation vetoed by the harness; rounds 7-13.)
// ---------------------------------------------------------------------------
__device__ int   g_is64;                            // 1 if edge_index is int64
__device__ int   g_cnt   [N_NODES];
__device__ int   g_fill  [N_NODES];
__device__ int   g_rowptr[N_NODES + 1];
__device__ int   g_blksum[128];                     // NB_SCAN <= 128
__device__ int   g_col   [N_EDGES];
__device__ float g_dinv  [N_NODES];
__device__ float g_Hs1   [(size_t)N_NODES * HID_C]; // X @ W1 (unscaled)
__device__ float g_X1    [(size_t)N_NODES * HID_C]; // relu layer-1 output
__device__ float g_Hs2   [(size_t)N_NODES * OUT_C]; // X1 @ W2 (unscaled)

// ---------------------------------------------------------------------------
// Edge-index dtype probe (int64 vs int32 staging — fixed the 717 trap)
// ---------------------------------------------------------------------------
__global__ void k_detect(const int* __restrict__ ei32) {
    if (blockIdx.x != 0 || threadIdx.x != 0) return;
    int allzero = 1;
    #pragma unroll 1
    for (int i = 1; i < 256; i += 2) {
        if (ei32[i] != 0) { allzero = 0; break; }
    }
    g_is64 = allzero;
}

__device__ __forceinline__ int edge_at(const void* ei, int e, int which) {
    int v;
    if (g_is64) {
        const long long* p = (const long long*)ei;
        v = (int)p[(size_t)which * N_EDGES + e];
    } else {
        const int* p = (const int*)ei;
        v = p[(size_t)which * N_EDGES + e];
    }
    v = (v < 0) ? 0 : v;
    v = (v >= N_NODES) ? (N_NODES - 1) : v;
    return v;
}

// ---------------------------------------------------------------------------
// CSR build: count -> scan -> fill  (int atomics only)
// ---------------------------------------------------------------------------
__global__ void k_prep() {
    int i = blockIdx.x * blockDim.x + threadIdx.x;
    if (i < N_NODES) { g_cnt[i] = 0; g_fill[i] = 0; }
}

__global__ void k_count(const void* __restrict__ ei) {
    int e = blockIdx.x * blockDim.x + threadIdx.x;
    if (e < N_EDGES) atomicAdd(&g_cnt[edge_at(ei, e, 1)], 1);
}

__global__ void k_dinv() {
    int i = blockIdx.x * blockDim.x + threadIdx.x;
    if (i < N_NODES) g_dinv[i] = rsqrtf(1.0f + (float)g_cnt[i]);  // +1 self loop
}

__global__ void k_scan1() {
    __shared__ int sh[SCAN_BLK];
    const int t = threadIdx.x;
    const int i = blockIdx.x * SCAN_BLK + t;
    int v = (i < N_NODES) ? g_cnt[i] : 0;
    sh[t] = v;
    __syncthreads();
    #pragma unroll
    for (int off = 1; off < SCAN_BLK; off <<= 1) {
        int x = (t >= off) ? sh[t - off] : 0;
        __syncthreads();
        sh[t] += x;
        __syncthreads();
    }
    if (i < N_NODES) g_rowptr[i] = sh[t] - v;
    if (t == SCAN_BLK - 1) g_blksum[blockIdx.x] = sh[t];
}

__global__ void k_scan2() {
    __shared__ int sh[128];
    const int t = threadIdx.x;
    int v = (t < NB_SCAN) ? g_blksum[t] : 0;
    sh[t] = v;
    __syncthreads();
    #pragma unroll
    for (int off = 1; off < 128; off <<= 1) {
        int x = (t >= off) ? sh[t - off] : 0;
        __syncthreads();
        sh[t] += x;
        __syncthreads();
    }
    if (t < NB_SCAN) g_blksum[t] = sh[t] - v;
}

__global__ void k_scan3() {
    int i = blockIdx.x * blockDim.x + threadIdx.x;
    if (i < N_NODES) g_rowptr[i] += g_blksum[i / SCAN_BLK];
    if (i == 0) g_rowptr[N_NODES] = N_EDGES;
}

__global__ void k_fill(const void* __restrict__ ei) {
    int e = blockIdx.x * blockDim.x + threadIdx.x;
    if (e >= N_EDGES) return;
    int d = edge_at(ei, e, 1);
    int pos = g_rowptr[d] + atomicAdd(&g_fill[d], 1);
    if (pos >= 0 && pos < N_EDGES) g_col[pos] = edge_at(ei, e, 0);
}

// ---------------------------------------------------------------------------
// SGEMM, f32x2 FMA, pair-along-M layout (LDS-minimal: 1.0 B/MAC, zero packs).
// Block: 128 threads, tile 128x128. Thread tile: 16 rows x 8 cols.
// acc[rp][c] = {C[2rp][c], C[2rp+1][c]} f32x2. A read as NATURAL contiguous
// pairs from As (no duplication); B stored DUPLICATED {b,b} in Bs.
// Per k-step/thread: 4 LDS.128 (A, 16 rows) + 4 LDS.128 (B-dup, 8 cols)
// = 128B for 128 MACs, 64 FMA2. Output UNSCALED (dinv applied in agg).
// ---------------------------------------------------------------------------
#define FMA_X2(acc, a2, b2) \
    asm("fma.rn.f32x2 %0, %1, %2, %0;" : "+l"(acc) : "l"(a2), "l"(b2))
#define UNPACK2(lo, hi, in) \
    asm("mov.b64 {%0, %1}, %2;" : "=r"(lo), "=r"(hi) : "l"(in))

template <int LAYER>
__global__ __launch_bounds__(128, 1) void k_gemm(const float* __restrict__ Xin,
                                                 const float* __restrict__ W)
{
    constexpr int N = (LAYER == 1) ? HID_C : OUT_C;
    constexpr int K = (LAYER == 1) ? IN_C  : HID_C;
    const float* __restrict__ A = (LAYER == 1) ? Xin : (const float*)g_X1;
    float* Hs = (LAYER == 1) ? g_Hs1 : g_Hs2;

    __shared__ float As[8][128];      // As[k][row]
    __shared__ float Bs[8][256];      // duplicated: Bs[k][2c]=Bs[k][2c+1]=B[k][c]

    const int tid = threadIdx.x;      // 0..127
    const int bm = blockIdx.x, bn = blockIdx.y;
    const int ty = tid >> 4;          // 0..7  -> rows ty*16 .. +15
    const int tx = tid & 15;          // 0..15 -> cols tx*8 .. +7

    // staging: A row = tid; B row = ty (k-row), cols tx*8..+7
    const int gRowA = bm * 128 + tid;
    const float* Aptr = A + (size_t)gRowA * K;
    const float* Bptr = W + (size_t)ty * N + bn * 128 + tx * 8;

    unsigned long long acc[8][8];     // [rowpair][col]
    #pragma unroll
    for (int i = 0; i < 8; i++)
        #pragma unroll
        for (int j = 0; j < 8; j++) acc[i][j] = 0ull;

    for (int k0 = 0; k0 < K; k0 += 8) {
        // ---- stage A: one row (8 k-values) per thread, transposed store ----
        {
            float4 a0 = make_float4(0.f, 0.f, 0.f, 0.f), a1 = a0;
            if (gRowA < N_NODES) {
                a0 = *(const float4*)(Aptr + k0);
                a1 = *(const float4*)(Aptr + k0 + 4);
            }
            As[0][tid] = a0.x; As[1][tid] = a0.y; As[2][tid] = a0.z; As[3][tid] = a0.w;
            As[4][tid] = a1.x; As[5][tid] = a1.y; As[6][tid] = a1.z; As[7][tid] = a1.w;
        }
        // ---- stage B: one k-row x 8 cols per thread, duplicated store ----
        {
            const float4 b0 = *(const float4*)(Bptr + (size_t)k0 * N);
            const float4 b1 = *(const float4*)(Bptr + (size_t)k0 * N + 4);
            float4* bd = (float4*)&Bs[ty][tx * 16];
            bd[0] = make_float4(b0.x, b0.x, b0.y, b0.y);
            bd[1] = make_float4(b0.z, b0.z, b0.w, b0.w);
            bd[2] = make_float4(b1.x, b1.x, b1.y, b1.y);
            bd[3] = make_float4(b1.z, b1.z, b1.w, b1.w);
        }
        __syncthreads();

        #pragma unroll
        for (int k = 0; k < 8; k++) {
            // A: 16 rows = 8 natural pairs (4 x LDS.128)
            ulonglong2 qa0 = *(const ulonglong2*)&As[k][ty * 16];
            ulonglong2 qa1 = *(const ulonglong2*)&As[k][ty * 16 + 4];
            ulonglong2 qa2 = *(const ulonglong2*)&As[k][ty * 16 + 8];
            ulonglong2 qa3 = *(const ulonglong2*)&As[k][ty * 16 + 12];
            // B: 8 duplicated cols (4 x LDS.128)
            ulonglong2 qb0 = *(const ulonglong2*)&Bs[k][tx * 16];
            ulonglong2 qb1 = *(const ulonglong2*)&Bs[k][tx * 16 + 4];
            ulonglong2 qb2 = *(const ulonglong2*)&Bs[k][tx * 16 + 8];
            ulonglong2 qb3 = *(const ulonglong2*)&Bs[k][tx * 16 + 12];
            #define COLFMA(rp, q) \
                FMA_X2(acc[rp][0], q, qb0.x); FMA_X2(acc[rp][1], q, qb0.y); \
                FMA_X2(acc[rp][2], q, qb1.x); FMA_X2(acc[rp][3], q, qb1.y); \
                FMA_X2(acc[rp][4], q, qb2.x); FMA_X2(acc[rp][5], q, qb2.y); \
                FMA_X2(acc[rp][6], q, qb3.x); FMA_X2(acc[rp][7], q, qb3.y)
            COLFMA(0, qa0.x); COLFMA(1, qa0.y);
            COLFMA(2, qa1.x); COLFMA(3, qa1.y);
            COLFMA(4, qa2.x); COLFMA(5, qa2.y);
            COLFMA(6, qa3.x); COLFMA(7, qa3.y);
            #undef COLFMA
        }
        __syncthreads();
    }

    // ---- epilogue: unpack row pairs, store UNSCALED ----
    #pragma unroll
    for (int rp = 0; rp < 8; rp++) {
        const int row0 = bm * 128 + ty * 16 + 2 * rp;
        const int row1 = row0 + 1;
        uint32_t lo0, hi0, lo1, hi1, lo2, hi2, lo3, hi3;
        uint32_t lo4, hi4, lo5, hi5, lo6, hi6, lo7, hi7;
        UNPACK2(lo0, hi0, acc[rp][0]); UNPACK2(lo1, hi1, acc[rp][1]);
        UNPACK2(lo2, hi2, acc[rp][2]); UNPACK2(lo3, hi3, acc[rp][3]);
        UNPACK2(lo4, hi4, acc[rp][4]); UNPACK2(lo5, hi5, acc[rp][5]);
        UNPACK2(lo6, hi6, acc[rp][6]); UNPACK2(lo7, hi7, acc[rp][7]);
        const size_t cb = (size_t)bn * 128 + tx * 8;
        if (row0 < N_NODES) {
            float* d0 = Hs + (size_t)row0 * N + cb;
            *(float4*)(d0)     = make_float4(__uint_as_float(lo0), __uint_as_float(lo1),
                                             __uint_as_float(lo2), __uint_as_float(lo3));
            *(float4*)(d0 + 4) = make_float4(__uint_as_float(lo4), __uint_as_float(lo5),
                                             __uint_as_float(lo6), __uint_as_float(lo7));
        }
        if (row1 < N_NODES) {
            float* d1 = Hs + (size_t)row1 * N + cb;
            *(float4*)(d1)     = make_float4(__uint_as_float(hi0), __uint_as_float(hi1),
                                             __uint_as_float(hi2), __uint_as_float(hi3));
            *(float4*)(d1 + 4) = make_float4(__uint_as_float(hi4), __uint_as_float(hi5),
                                             __uint_as_float(hi6), __uint_as_float(hi7));
        }
    }
}

// ---------------------------------------------------------------------------
// Aggregation (pure gather), unroll 4. dinv applied here:
// out[d] = dinv[d] * ( dinv[d]*H[d] + sum_s dinv[s]*H[s] ) + bias
// ---------------------------------------------------------------------------
__global__ __launch_bounds__(128) void k_agg1(const float* __restrict__ bias) {
    const int d = blockIdx.x;
    const int t = threadIdx.x;                         // 128 = HID_C/4
    const float4* base = (const float4*)g_Hs1;
    const float dd = g_dinv[d];
    float4 self = base[(size_t)d * 128 + t];
    float4 acc;
    acc.x = self.x * dd; acc.y = self.y * dd;
    acc.z = self.z * dd; acc.w = self.w * dd;
    const int beg = g_rowptr[d], end = g_rowptr[d + 1];
    int j = beg;
    for (; j + 3 < end; j += 4) {
        int s0 = g_col[j], s1 = g_col[j + 1], s2 = g_col[j + 2], s3 = g_col[j + 3];
        float w0 = g_dinv[s0], w1 = g_dinv[s1], w2 = g_dinv[s2], w3 = g_dinv[s3];
        float4 v0 = base[(size_t)s0 * 128 + t];
        float4 v1 = base[(size_t)s1 * 128 + t];
        float4 v2 = base[(size_t)s2 * 128 + t];
        float4 v3 = base[(size_t)s3 * 128 + t];
        acc.x += (v0.x * w0 + v1.x * w1) + (v2.x * w2 + v3.x * w3);
        acc.y += (v0.y * w0 + v1.y * w1) + (v2.y * w2 + v3.y * w3);
        acc.z += (v0.z * w0 + v1.z * w1) + (v2.z * w2 + v3.z * w3);
        acc.w += (v0.w * w0 + v1.w * w1) + (v2.w * w2 + v3.w * w3);
    }
    for (; j < end; j++) {
        int s0 = g_col[j];
        float w0 = g_dinv[s0];
        float4 v0 = base[(size_t)s0 * 128 + t];
        acc.x += v0.x * w0; acc.y += v0.y * w0;
        acc.z += v0.z * w0; acc.w += v0.w * w0;
    }
    float4 b = ((const float4*)bias)[t];
    float4 r;
    r.x = fmaxf(acc.x * dd + b.x, 0.f);
    r.y = fmaxf(acc.y * dd + b.y, 0.f);
    r.z = fmaxf(acc.z * dd + b.z, 0.f);
    r.w = fmaxf(acc.w * dd + b.w, 0.f);
    ((float4*)g_X1)[(size_t)d * 128 + t] = r;
}

__global__ __launch_bounds__(64) void k_agg2(const float* __restrict__ bias,
                                             float* __restrict__ out) {
    const int d = blockIdx.x;
    const int t = threadIdx.x;                         // 64 = OUT_C/4
    const float4* base = (const float4*)g_Hs2;
    const float dd = g_dinv[d];
    float4 self = base[(size_t)d * 64 + t];
    float4 acc;
    acc.x = self.x * dd; acc.y = self.y * dd;
    acc.z = self.z * dd; acc.w = self.w * dd;
    const int beg = g_rowptr[d], end = g_rowptr[d + 1];
    int j = beg;
    for (; j + 3 < end; j += 4) {
        int s0 = g_col[j], s1 = g_col[j + 1], s2 = g_col[j + 2], s3 = g_col[j + 3];
        float w0 = g_dinv[s0], w1 = g_dinv[s1], w2 = g_dinv[s2], w3 = g_dinv[s3];
        float4 v0 = base[(size_t)s0 * 64 + t];
        float4 v1 = base[(size_t)s1 * 64 + t];
        float4 v2 = base[(size_t)s2 * 64 + t];
        float4 v3 = base[(size_t)s3 * 64 + t];
        acc.x += (v0.x * w0 + v1.x * w1) + (v2.x * w2 + v3.x * w3);
        acc.y += (v0.y * w0 + v1.y * w1) + (v2.y * w2 + v3.y * w3);
        acc.z += (v0.z * w0 + v1.z * w1) + (v2.z * w2 + v3.z * w3);
        acc.w += (v0.w * w0 + v1.w * w1) + (v2.w * w2 + v3.w * w3);
    }
    for (; j < end; j++) {
        int s0 = g_col[j];
        float w0 = g_dinv[s0];
        float4 v0 = base[(size_t)s0 * 64 + t];
        acc.x += v0.x * w0; acc.y += v0.y * w0;
        acc.z += v0.z * w0; acc.w += v0.w * w0;
    }
    float4 b = ((const float4*)bias)[t];
    float4 r;
    r.x = acc.x * dd + b.x;
    r.y = acc.y * dd + b.y;
    r.z = acc.z * dd + b.z;
    r.w = acc.w * dd + b.w;
    ((float4*)out)[(size_t)d * 64 + t] = r;
}

// ---------------------------------------------------------------------------
// Launch. gemm1 is MY 4th launch so the harness ncu capture (overall #6 =
// 2 hidden + my #4) profiles the GEMM.
// ---------------------------------------------------------------------------
extern "C" void kernel_launch(void* const* d_in, const int* in_sizes, int n_in,
                              void* d_out, int out_size)
{
    const float* x   = (const float*)d_in[0];
    const void*  ei  = d_in[1];                 // [2, E]; int32 or int64 (probed)
    const float* w1  = (const float*)d_in[2];
    const float* b1  = (const float*)d_in[3];
    const float* w2  = (const float*)d_in[4];
    const float* b2  = (const float*)d_in[5];
    float*       out = (float*)d_out;

    // 1-3) probe + CSR prep + degree count
    k_detect<<<1, 32>>>((const int*)ei);
    k_prep <<<(N_NODES + 255) / 256, 256>>>();
    k_count<<<(N_EDGES + 255) / 256, 256>>>(ei);

    // 4) Layer-1 GEMM (profiled launch)
    {
        dim3 grid((N_NODES + 127) / 128, HID_C / 128);
        k_gemm<1><<<grid, 128>>>(x, w1);
    }

    // 5-9) dinv + finish CSR build
    k_dinv <<<(N_NODES + 255) / 256, 256>>>();
    k_scan1<<<NB_SCAN, SCAN_BLK>>>();
    k_scan2<<<1, 128>>>();
    k_scan3<<<(N_NODES + 255) / 256, 256>>>();
    k_fill <<<(N_EDGES + 255) / 256, 256>>>(ei);

    // 10) layer-1 aggregation (applies dinv, bias, relu)
    k_agg1<<<N_NODES, 128>>>(b1);

    // 11) Layer-2 GEMM
    {
        dim3 grid((N_NODES + 127) / 128, OUT_C / 128);
        k_gemm<2><<<grid, 128>>>(x /*unused*/, w2);
    }
    // 12) layer-2 aggregation
    k_agg2<<<N_NODES, 64>>>(b2, out);
}

// round 17
// speedup vs baseline: 1.6648x; 1.6648x over previous
#include <cuda_runtime.h>
#include <cstdint>

// Problem constants (fixed by the dataset)
#define N_NODES 50000
#define N_EDGES 800000
#define IN_C    512
#define HID_C   512
#define OUT_C   256

#define SCAN_BLK 512
#define NB_SCAN  ((N_NODES + SCAN_BLK - 1) / SCAN_BLK)   // 98

// ---------------------------------------------------------------------------
// Scratch: __device__ globals, referenced directly inside kernels.
// (No tensor-core instructions anywhere: modules containing ldmatrix/mma.sync
// trigger a fixed 128MiB driver allocation vetoed by the harness; rounds 7-13.)
// ---------------------------------------------------------------------------
__device__ int   g_is64;                            // 1 if edge_index is int64
__device__ int   g_cnt   [N_NODES];
__device__ int   g_fill  [N_NODES];
__device__ int   g_rowptr[N_NODES + 1];
__device__ int   g_blksum[128];                     // NB_SCAN <= 128
__device__ int   g_col   [N_EDGES];
__device__ float g_dinv  [N_NODES];
__device__ float g_Hs1   [(size_t)N_NODES * HID_C]; // dinv[r] * (X @ W1)
__device__ float g_X1    [(size_t)N_NODES * HID_C]; // relu layer-1 output
__device__ float g_Hs2   [(size_t)N_NODES * OUT_C]; // dinv[r] * (X1 @ W2)

// ---------------------------------------------------------------------------
// init: zero counters; block 0 thread 0 also probes edge_index dtype.
// int64 values in [0, 50000) -> every odd 32-bit word is 0.
// ---------------------------------------------------------------------------
__global__ void k_init(const int* __restrict__ ei32) {
    int i = blockIdx.x * blockDim.x + threadIdx.x;
    if (i < N_NODES) { g_cnt[i] = 0; g_fill[i] = 0; }
    if (blockIdx.x == 0 && threadIdx.x == 0) {
        int allzero = 1;
        #pragma unroll 1
        for (int k = 1; k < 256; k += 2) {
            if (ei32[k] != 0) { allzero = 0; break; }
        }
        g_is64 = allzero;
    }
}

__device__ __forceinline__ int edge_at(const void* ei, int e, int which) {
    int v;
    if (g_is64) {
        const long long* p = (const long long*)ei;
        v = (int)p[(size_t)which * N_EDGES + e];
    } else {
        const int* p = (const int*)ei;
        v = p[(size_t)which * N_EDGES + e];
    }
    v = (v < 0) ? 0 : v;
    v = (v >= N_NODES) ? (N_NODES - 1) : v;
    return v;
}

// ---------------------------------------------------------------------------
// CSR build: count -> scan -> fill  (int atomics only)
// ---------------------------------------------------------------------------
__global__ void k_count(const void* __restrict__ ei) {
    int e = blockIdx.x * blockDim.x + threadIdx.x;
    if (e < N_EDGES) atomicAdd(&g_cnt[edge_at(ei, e, 1)], 1);
}

__global__ void k_dinv() {
    int i = blockIdx.x * blockDim.x + threadIdx.x;
    if (i < N_NODES) g_dinv[i] = rsqrtf(1.0f + (float)g_cnt[i]);  // +1 self loop
}

__global__ void k_scan1() {
    __shared__ int sh[SCAN_BLK];
    const int t = threadIdx.x;
    const int i = blockIdx.x * SCAN_BLK + t;
    int v = (i < N_NODES) ? g_cnt[i] : 0;
    sh[t] = v;
    __syncthreads();
    #pragma unroll
    for (int off = 1; off < SCAN_BLK; off <<= 1) {
        int x = (t >= off) ? sh[t - off] : 0;
        __syncthreads();
        sh[t] += x;
        __syncthreads();
    }
    if (i < N_NODES) g_rowptr[i] = sh[t] - v;        // exclusive (block-local)
    if (t == SCAN_BLK - 1) g_blksum[blockIdx.x] = sh[t];
}

__global__ void k_scan2() {
    __shared__ int sh[128];
    const int t = threadIdx.x;
    int v = (t < NB_SCAN) ? g_blksum[t] : 0;
    sh[t] = v;
    __syncthreads();
    #pragma unroll
    for (int off = 1; off < 128; off <<= 1) {
        int x = (t >= off) ? sh[t - off] : 0;
        __syncthreads();
        sh[t] += x;
        __syncthreads();
    }
    if (t < NB_SCAN) g_blksum[t] = sh[t] - v;
}

__global__ void k_scan3() {
    int i = blockIdx.x * blockDim.x + threadIdx.x;
    if (i < N_NODES) g_rowptr[i] += g_blksum[i / SCAN_BLK];
    if (i == 0) g_rowptr[N_NODES] = N_EDGES;
}

__global__ void k_fill(const void* __restrict__ ei) {
    int e = blockIdx.x * blockDim.x + threadIdx.x;
    if (e >= N_EDGES) return;
    int d = edge_at(ei, e, 1);
    int pos = g_rowptr[d] + atomicAdd(&g_fill[d], 1);
    if (pos >= 0 && pos < N_EDGES) g_col[pos] = edge_at(ei, e, 0);
}

// ---------------------------------------------------------------------------
// SGEMM 128x128x8 fp32, f32x2 packed FMA — the round-11 measured-best kernel,
// restored verbatim. 256 threads, 8x8 thread tile, single-buffered smem,
// epilogue scales row by dinv[row]. (All restructures — dup-A, dup-B big
// tile, double-buffer — measured slower; occ>=16 warps/SM is load-bearing.)
// ---------------------------------------------------------------------------
#define FMA_X2(acc, a2, b2) \
    asm("fma.rn.f32x2 %0, %1, %2, %0;" : "+l"(acc) : "l"(a2), "l"(b2))
#define PACK_AA(out, abits) \
    asm("mov.b64 %0, {%1, %1};" : "=l"(out) : "r"(abits))
#define UNPACK2(lo, hi, in) \
    asm("mov.b64 {%0, %1}, %2;" : "=r"(lo), "=r"(hi) : "l"(in))

template <int LAYER>
__global__ __launch_bounds__(256) void k_gemm(const float* __restrict__ Xin,
                                              const float* __restrict__ W)
{
    constexpr int N = (LAYER == 1) ? HID_C : OUT_C;
    constexpr int K = (LAYER == 1) ? IN_C  : HID_C;
    const float* __restrict__ A = (LAYER == 1) ? Xin : (const float*)g_X1;
    float* Hs = (LAYER == 1) ? g_Hs1 : g_Hs2;

    __shared__ float As[8][128];
    __shared__ float Bs[8][128];

    const int tid = threadIdx.x;
    const int bm = blockIdx.x, bn = blockIdx.y;

    const int aRow = tid >> 1;
    const int aCol = (tid & 1) * 4;
    const int bRow = tid >> 5;
    const int bCol = (tid & 31) * 4;

    const int ty = tid >> 4;
    const int tx = tid & 15;

    const int gRowA = bm * 128 + aRow;
    const float* Aptr = A + (size_t)gRowA * K + aCol;
    const float* Bptr = W + (size_t)bRow * N + bn * 128 + bCol;

    unsigned long long acc[8][4];
    #pragma unroll
    for (int i = 0; i < 8; i++)
        #pragma unroll
        for (int j = 0; j < 4; j++) acc[i][j] = 0ull;

    for (int k0 = 0; k0 < K; k0 += 8) {
        float4 a4 = make_float4(0.f, 0.f, 0.f, 0.f);
        if (gRowA < N_NODES) a4 = *(const float4*)(Aptr + k0);
        As[aCol + 0][aRow] = a4.x;
        As[aCol + 1][aRow] = a4.y;
        As[aCol + 2][aRow] = a4.z;
        As[aCol + 3][aRow] = a4.w;

        float4 b4 = *(const float4*)(Bptr + (size_t)k0 * N);
        *(float4*)&Bs[bRow][bCol] = b4;

        __syncthreads();

        #pragma unroll
        for (int k = 0; k < 8; k++) {
            float ra[8];
            *(float4*)(ra)     = *(const float4*)&As[k][ty * 8];
            *(float4*)(ra + 4) = *(const float4*)&As[k][ty * 8 + 4];
            ulonglong2 p0 = *(const ulonglong2*)&Bs[k][tx * 8];
            ulonglong2 p1 = *(const ulonglong2*)&Bs[k][tx * 8 + 4];
            #pragma unroll
            for (int i = 0; i < 8; i++) {
                unsigned long long ai;
                PACK_AA(ai, __float_as_uint(ra[i]));
                FMA_X2(acc[i][0], ai, p0.x);
                FMA_X2(acc[i][1], ai, p0.y);
                FMA_X2(acc[i][2], ai, p1.x);
                FMA_X2(acc[i][3], ai, p1.y);
            }
        }
        __syncthreads();
    }

    #pragma unroll
    for (int i = 0; i < 8; i++) {
        const int row = bm * 128 + ty * 8 + i;
        if (row >= N_NODES) continue;
        const float s = g_dinv[row];
        const size_t base = (size_t)row * N + bn * 128 + tx * 8;
        uint32_t u0, u1, u2, u3;
        UNPACK2(u0, u1, acc[i][0]);
        UNPACK2(u2, u3, acc[i][1]);
        float4 v0 = make_float4(__uint_as_float(u0) * s, __uint_as_float(u1) * s,
                                __uint_as_float(u2) * s, __uint_as_float(u3) * s);
        UNPACK2(u0, u1, acc[i][2]);
        UNPACK2(u2, u3, acc[i][3]);
        float4 v1 = make_float4(__uint_as_float(u0) * s, __uint_as_float(u1) * s,
                                __uint_as_float(u2) * s, __uint_as_float(u3) * s);
        *(float4*)(Hs + base)     = v0;
        *(float4*)(Hs + base + 4) = v1;
    }
}

// ---------------------------------------------------------------------------
// Aggregation (pure gather), UNROLL 8 for memory-level parallelism.
// Hs rows are pre-scaled by dinv[src] (GEMM epilogue), so the inner loop is
// pure sums: acc = Hs[d] + sum_j Hs[col[j]]; then dinv[d]/bias/(relu).
// ---------------------------------------------------------------------------
__global__ __launch_bounds__(128) void k_agg1(const float* __restrict__ bias) {
    const int d = blockIdx.x;
    const int t = threadIdx.x;                         // 128 = HID_C/4
    const float4* base = (const float4*)g_Hs1;
    float4 acc = base[(size_t)d * 128 + t];
    const int beg = g_rowptr[d], end = g_rowptr[d + 1];
    int j = beg;
    for (; j + 7 < end; j += 8) {
        int s0 = g_col[j],     s1 = g_col[j + 1], s2 = g_col[j + 2], s3 = g_col[j + 3];
        int s4 = g_col[j + 4], s5 = g_col[j + 5], s6 = g_col[j + 6], s7 = g_col[j + 7];
        float4 v0 = base[(size_t)s0 * 128 + t];
        float4 v1 = base[(size_t)s1 * 128 + t];
        float4 v2 = base[(size_t)s2 * 128 + t];
        float4 v3 = base[(size_t)s3 * 128 + t];
        float4 v4 = base[(size_t)s4 * 128 + t];
        float4 v5 = base[(size_t)s5 * 128 + t];
        float4 v6 = base[(size_t)s6 * 128 + t];
        float4 v7 = base[(size_t)s7 * 128 + t];
        acc.x += ((v0.x + v1.x) + (v2.x + v3.x)) + ((v4.x + v5.x) + (v6.x + v7.x));
        acc.y += ((v0.y + v1.y) + (v2.y + v3.y)) + ((v4.y + v5.y) + (v6.y + v7.y));
        acc.z += ((v0.z + v1.z) + (v2.z + v3.z)) + ((v4.z + v5.z) + (v6.z + v7.z));
        acc.w += ((v0.w + v1.w) + (v2.w + v3.w)) + ((v4.w + v5.w) + (v6.w + v7.w));
    }
    for (; j + 1 < end; j += 2) {
        int s0 = g_col[j], s1 = g_col[j + 1];
        float4 v0 = base[(size_t)s0 * 128 + t];
        float4 v1 = base[(size_t)s1 * 128 + t];
        acc.x += v0.x + v1.x; acc.y += v0.y + v1.y;
        acc.z += v0.z + v1.z; acc.w += v0.w + v1.w;
    }
    if (j < end) {
        int s0 = g_col[j];
        float4 v0 = base[(size_t)s0 * 128 + t];
        acc.x += v0.x; acc.y += v0.y; acc.z += v0.z; acc.w += v0.w;
    }
    const float sc = g_dinv[d];
    float4 b = ((const float4*)bias)[t];
    float4 r;
    r.x = fmaxf(acc.x * sc + b.x, 0.f);
    r.y = fmaxf(acc.y * sc + b.y, 0.f);
    r.z = fmaxf(acc.z * sc + b.z, 0.f);
    r.w = fmaxf(acc.w * sc + b.w, 0.f);
    ((float4*)g_X1)[(size_t)d * 128 + t] = r;
}

__global__ __launch_bounds__(64) void k_agg2(const float* __restrict__ bias,
                                             float* __restrict__ out) {
    const int d = blockIdx.x;
    const int t = threadIdx.x;                         // 64 = OUT_C/4
    const float4* base = (const float4*)g_Hs2;
    float4 acc = base[(size_t)d * 64 + t];
    const int beg = g_rowptr[d], end = g_rowptr[d + 1];
    int j = beg;
    for (; j + 7 < end; j += 8) {
        int s0 = g_col[j],     s1 = g_col[j + 1], s2 = g_col[j + 2], s3 = g_col[j + 3];
        int s4 = g_col[j + 4], s5 = g_col[j + 5], s6 = g_col[j + 6], s7 = g_col[j + 7];
        float4 v0 = base[(size_t)s0 * 64 + t];
        float4 v1 = base[(size_t)s1 * 64 + t];
        float4 v2 = base[(size_t)s2 * 64 + t];
        float4 v3 = base[(size_t)s3 * 64 + t];
        float4 v4 = base[(size_t)s4 * 64 + t];
        float4 v5 = base[(size_t)s5 * 64 + t];
        float4 v6 = base[(size_t)s6 * 64 + t];
        float4 v7 = base[(size_t)s7 * 64 + t];
        acc.x += ((v0.x + v1.x) + (v2.x + v3.x)) + ((v4.x + v5.x) + (v6.x + v7.x));
        acc.y += ((v0.y + v1.y) + (v2.y + v3.y)) + ((v4.y + v5.y) + (v6.y + v7.y));
        acc.z += ((v0.z + v1.z) + (v2.z + v3.z)) + ((v4.z + v5.z) + (v6.z + v7.z));
        acc.w += ((v0.w + v1.w) + (v2.w + v3.w)) + ((v4.w + v5.w) + (v6.w + v7.w));
    }
    for (; j + 1 < end; j += 2) {
        int s0 = g_col[j], s1 = g_col[j + 1];
        float4 v0 = base[(size_t)s0 * 64 + t];
        float4 v1 = base[(size_t)s1 * 64 + t];
        acc.x += v0.x + v1.x; acc.y += v0.y + v1.y;
        acc.z += v0.z + v1.z; acc.w += v0.w + v1.w;
    }
    if (j < end) {
        int s0 = g_col[j];
        float4 v0 = base[(size_t)s0 * 64 + t];
        acc.x += v0.x; acc.y += v0.y; acc.z += v0.z; acc.w += v0.w;
    }
    const float sc = g_dinv[d];
    float4 b = ((const float4*)bias)[t];
    float4 r;
    r.x = acc.x * sc + b.x;
    r.y = acc.y * sc + b.y;
    r.z = acc.z * sc + b.z;
    r.w = acc.w * sc + b.w;
    ((float4*)out)[(size_t)d * 64 + t] = r;
}

// ---------------------------------------------------------------------------
// Launch. gemm1 is MY 4th launch (overall #6 = 2 hidden + my #4) so the
// harness ncu capture profiles the GEMM.
// ---------------------------------------------------------------------------
extern "C" void kernel_launch(void* const* d_in, const int* in_sizes, int n_in,
                              void* d_out, int out_size)
{
    const float* x   = (const float*)d_in[0];
    const void*  ei  = d_in[1];                 // [2, E]; int32 or int64 (probed)
    const float* w1  = (const float*)d_in[2];
    const float* b1  = (const float*)d_in[3];
    const float* w2  = (const float*)d_in[4];
    const float* b2  = (const float*)d_in[5];
    float*       out = (float*)d_out;

    // 1) init (zero counters + dtype probe)
    k_init <<<(N_NODES + 255) / 256, 256>>>((const int*)ei);
    // 2) degree count
    k_count<<<(N_EDGES + 255) / 256, 256>>>(ei);
    // 3) dinv
    k_dinv <<<(N_NODES + 255) / 256, 256>>>();

    // 4) Layer-1 GEMM (profiled launch)
    {
        dim3 grid((N_NODES + 127) / 128, HID_C / 128);
        k_gemm<1><<<grid, 256>>>(x, w1);
    }

    // 5-8) finish CSR build
    k_scan1<<<NB_SCAN, SCAN_BLK>>>();
    k_scan2<<<1, 128>>>();
    k_scan3<<<(N_NODES + 255) / 256, 256>>>();
    k_fill <<<(N_EDGES + 255) / 256, 256>>>(ei);

    // 9) layer-1 aggregation
    k_agg1<<<N_NODES, 128>>>(b1);

    // 10) Layer-2 GEMM
    {
        dim3 grid((N_NODES + 127) / 128, OUT_C / 128);
        k_gemm<2><<<grid, 256>>>(x /*unused*/, w2);
    }
    // 11) layer-2 aggregation
    k_agg2<<<N_NODES, 64>>>(b2, out);
}